// round 14
// baseline (speedup 1.0000x reference)
#include <cuda_runtime.h>
#include <cstdint>

#define T_STEPS 256
#define BATCH   128
#define KDIM    1536
#define F4      384     // KDIM/4 (float4 units)
#define NTHR    128
#define STAGE_B 6144u   // F4 * 16 bytes

// HW tanh: single MUFU op, max rel err ~2^-11.
__device__ __forceinline__ float tanha(float x) {
    float y;
    asm("tanh.approx.f32 %0, %1;" : "=f"(y) : "f"(x));
    return y;
}

__device__ __forceinline__ void cp_async16(uint32_t dst, const void* src) {
    asm volatile("cp.async.cg.shared.global [%0], [%1], 16;" :: "r"(dst), "l"(src));
}
#define CP_COMMIT() asm volatile("cp.async.commit_group;" ::: "memory")
#define CP_WAIT3()  asm volatile("cp.async.wait_group 3;" ::: "memory")

// packed f32x2 fma
__device__ __forceinline__ void ffma2(unsigned long long& acc,
                                      unsigned long long a,
                                      unsigned long long b) {
    asm("fma.rn.f32x2 %0, %1, %2, %0;" : "+l"(acc) : "l"(a), "l"(b));
}
__device__ __forceinline__ float2 unpack2(unsigned long long v) {
    float2 f;
    asm("mov.b64 {%0, %1}, %2;" : "=f"(f.x), "=f"(f.y) : "l"(v));
    return f;
}

// 12-term dot product (3 float4 each side), 2 accumulator chains.
__device__ __forceinline__ float dot12(const float4* v, const float4* w) {
    float a0 = 0.0f, a1 = 0.0f;
    #pragma unroll
    for (int j = 0; j < 3; j++) {
        a0 = fmaf(v[j].x, w[j].x, fmaf(v[j].y, w[j].y, a0));
        a1 = fmaf(v[j].z, w[j].z, fmaf(v[j].w, w[j].w, a1));
    }
    return a0 + a1;
}

// ---------------------------------------------------------------------------
// One CTA per batch, 128 threads (4 warps). Strided float4 ownership
// (tid + 128*j): fully coalesced. 4-stage cp.async input ring, unrolled by 4.
// Critical path per step: gate dots -> 4-sum butterfly (6 SHFL) -> STS ->
// barrier -> 4-wide tail -> 6 broadcasts -> tanh.approx update.
// The x-projection for step t+2 (LDS + FFMA2 + 2-sum butterfly + STS into the
// OTHER sPart buffer) runs entirely inside step t's MUFU-drain shadow, so the
// pre-barrier serial section carries no x work at all.
// ---------------------------------------------------------------------------
__global__ void __launch_bounds__(NTHR) fused_kernel(
    const float* __restrict__ inputs,
    const float* __restrict__ h0,
    const float* __restrict__ c0,
    const float* __restrict__ Wr,
    const float* __restrict__ br,
    const float* __restrict__ Wc,
    const float* __restrict__ bc,
    const float* __restrict__ Wi,
    const float* __restrict__ bi,
    float* __restrict__ out)
{
    __shared__ float      sPart[2][8][4];   // [buf][row][warp]; rows 0-5 used
    __shared__ ulonglong2 sX[4 * F4];       // 4 x 6KB input stages (packed)

    const int tid  = threadIdx.x;
    const int b    = blockIdx.x;
    const int warp = tid >> 5;
    const int lane = tid & 31;

    const float4*     in4 = (const float4*)inputs;
    const float4*     Wr4 = (const float4*)Wr;
    const float4*     Wc4 = (const float4*)Wc;
    const ulonglong2* Wi2 = (const ulonglong2*)Wi;
    float4* out4 = (float4*)out;

    float4 h[3], c[3], wr0[3], wr1[3], wc0[3], wc1[3];
    ulonglong2 wi0p[3], wi1p[3];
    #pragma unroll
    for (int j = 0; j < 3; j++) {
        const int p = tid + 128 * j;           // strided ownership: coalesced
        h[j]    = ((const float4*)h0)[b * F4 + p];
        c[j]    = ((const float4*)c0)[b * F4 + p];
        wr0[j]  = Wr4[p];        wr1[j]  = Wr4[F4 + p];
        wc0[j]  = Wc4[p];        wc1[j]  = Wc4[F4 + p];
        wi0p[j] = Wi2[p];        wi1p[j] = Wi2[F4 + p];
    }
    const float br0 = br[0], br1 = br[1];
    const float bc0 = bc[0], bc1 = bc[1];
    const float bi0 = bi[0], bi1 = bi[1];

    const int rid = lane & 7;
    const float mybias = (rid == 0) ? br0 : (rid == 1) ? br1
                       : (rid == 2) ? bc0 : (rid == 3) ? bc1
                       : (rid == 4) ? bi0 : (rid == 5) ? bi1 : 0.0f;

    const bool lo = lane < 16;
    const bool b3 = (lane & 8) != 0;

    // zero unused tail rows (6,7) in both buffers
    if (tid < 16) {
        const int bf = tid >> 3, r = 6 + ((tid >> 2) & 1), col = tid & 3;
        sPart[bf][r][col] = 0.0f;
    }

    const uint32_t sx_tid =
        (uint32_t)__cvta_generic_to_shared(&sX[0]) + (uint32_t)tid * 16u;
    const ulonglong2* sXu = &sX[0];

    // ---- prologue ----
    // Xc,Xh = proj(x_0); sPart[0][4,5] = partials of proj(x_1);
    // stages 2,3,0,1 <- x_2..x_5.
    {
        float4 x0[3], x1[3], wi0f[3], wi1f[3];
        #pragma unroll
        for (int j = 0; j < 3; j++) {
            const int p = tid + 128 * j;
            x0[j]   = in4[(long)b * F4 + p];
            x1[j]   = in4[(long)(BATCH + b) * F4 + p];
            wi0f[j] = *(const float4*)&wi0p[j];
            wi1f[j] = *(const float4*)&wi1p[j];
        }
        float p0c = dot12(x0, wi0f), p0h = dot12(x0, wi1f);
        float p1c = dot12(x1, wi0f), p1h = dot12(x1, wi1f);

        #pragma unroll
        for (int s = 2; s <= 5; s++) {
            const float4* src = in4 + (long)s * BATCH * F4 + (long)b * F4 + tid;
            const uint32_t dst = sx_tid + (uint32_t)(s & 3) * STAGE_B;
            cp_async16(dst,         src);
            cp_async16(dst + 2048u, src + 128);
            cp_async16(dst + 4096u, src + 256);
            CP_COMMIT();
        }

        // 2-sum butterflies for proj(x_0) -> sPart[1][4,5], proj(x_1) -> sPart[0][4,5]
        float k0 = lo ? p0c : p0h;
        float s0 = lo ? p0h : p0c;
        k0 += __shfl_xor_sync(~0u, s0, 16);
        k0 += __shfl_xor_sync(~0u, k0, 8);
        k0 += __shfl_xor_sync(~0u, k0, 4);
        k0 += __shfl_xor_sync(~0u, k0, 2);
        k0 += __shfl_xor_sync(~0u, k0, 1);
        float k1 = lo ? p1c : p1h;
        float s1 = lo ? p1h : p1c;
        k1 += __shfl_xor_sync(~0u, s1, 16);
        k1 += __shfl_xor_sync(~0u, k1, 8);
        k1 += __shfl_xor_sync(~0u, k1, 4);
        k1 += __shfl_xor_sync(~0u, k1, 2);
        k1 += __shfl_xor_sync(~0u, k1, 1);
        if (lane == 0)  { sPart[1][4][warp] = k0; sPart[0][4][warp] = k1; }
        if (lane == 16) { sPart[1][5][warp] = k0; sPart[0][5][warp] = k1; }
    }
    __syncthreads();
    float Xc, Xh;
    {
        float4 q4 = *(const float4*)sPart[1][4];
        float4 q5 = *(const float4*)sPart[1][5];
        Xc = (q4.x + q4.y) + (q4.z + q4.w) + bi0;
        Xh = (q5.x + q5.y) + (q5.z + q5.w) + bi1;
    }

    // strength-reduced pointers
    const float4* srcp = in4 + (long)6 * BATCH * F4 + (long)b * F4 + tid; // x_{t+6}
    float4*       outp = out4 + (long)b * F4 + tid;

#define DO_STEP(SC2, BUF, SRC)                                                 \
    {                                                                          \
        /* phase A: gate dots + 4-sum butterfly (6 SHFL) */                    \
        float g0 = dot12(h, wr0), g1 = dot12(h, wr1);                          \
        float g2 = dot12(c, wc0), g3 = dot12(c, wc1);                          \
        float sA = lo ? g2 : g0;                                               \
        float rA = __shfl_xor_sync(~0u, sA, 16);                               \
        float sB = lo ? g3 : g1;                                               \
        float rB = __shfl_xor_sync(~0u, sB, 16);                               \
        float u0 = (lo ? g0 : g2) + rA;                                        \
        float u1 = (lo ? g1 : g3) + rB;                                        \
        float keep = b3 ? u1 : u0;                                             \
        float send = b3 ? u0 : u1;                                             \
        float R = keep + __shfl_xor_sync(~0u, send, 8);                        \
        R += __shfl_xor_sync(~0u, R, 4);                                       \
        R += __shfl_xor_sync(~0u, R, 2);                                       \
        R += __shfl_xor_sync(~0u, R, 1);                                       \
        if ((lane & 7) == 0) sPart[BUF][lane >> 3][warp] = R;                  \
        __syncthreads();                                                       \
        /* tail: 4 cross-warp partials of row rid */                           \
        float4 qv = *(const float4*)sPart[BUF][rid];                           \
        float s = (qv.x + qv.y) + (qv.z + qv.w) + mybias;                      \
        float gval;                                                            \
        if (rid < 4) {                                                         \
            float sg  = fmaf(-0.5f, tanha(0.5f * s), 0.5f);                    \
            float fac = (rid == 0) ? Xc : (rid == 3) ? Xh : 1.0f;              \
            gval = sg * fac;                                                   \
        } else {                                                               \
            gval = s;                                                          \
        }                                                                      \
        const float gca = __shfl_sync(~0u, gval, 0);                           \
        const float ghb = __shfl_sync(~0u, gval, 1);                           \
        const float gcb = __shfl_sync(~0u, gval, 2);                           \
        const float gha = __shfl_sync(~0u, gval, 3);                           \
        Xc = __shfl_sync(~0u, gval, 4);                                        \
        Xh = __shfl_sync(~0u, gval, 5);                                        \
        /* phase C (shadowed by MUFU drain): x-proj for t+2 -> other buffer */ \
        CP_WAIT3();                                                            \
        const ulonglong2* xs = sXu + (SC2) * F4 + tid;                         \
        ulonglong2 xv0 = xs[0], xv1 = xs[128], xv2 = xs[256];                  \
        {   /* refill stage SC2 with x from SRC */                             \
            const uint32_t dst = sx_tid + (uint32_t)(SC2) * STAGE_B;           \
            cp_async16(dst,         (SRC));                                    \
            cp_async16(dst + 2048u, (SRC) + 128);                              \
            cp_async16(dst + 4096u, (SRC) + 256);                              \
            CP_COMMIT();                                                       \
        }                                                                      \
        unsigned long long a0 = 0ull, a1 = 0ull, q0_ = 0ull, q1_ = 0ull;       \
        ffma2(a0, xv0.x, wi0p[0].x); ffma2(a1, xv0.y, wi0p[0].y);              \
        ffma2(q0_, xv0.x, wi1p[0].x); ffma2(q1_, xv0.y, wi1p[0].y);            \
        ffma2(a0, xv1.x, wi0p[1].x); ffma2(a1, xv1.y, wi0p[1].y);              \
        ffma2(q0_, xv1.x, wi1p[1].x); ffma2(q1_, xv1.y, wi1p[1].y);            \
        ffma2(a0, xv2.x, wi0p[2].x); ffma2(a1, xv2.y, wi0p[2].y);              \
        ffma2(q0_, xv2.x, wi1p[2].x); ffma2(q1_, xv2.y, wi1p[2].y);            \
        float2 pa0 = unpack2(a0), pa1 = unpack2(a1);                           \
        float2 pb0 = unpack2(q0_), pb1 = unpack2(q1_);                         \
        float x4 = (pa0.x + pa0.y) + (pa1.x + pa1.y);                          \
        float x5 = (pb0.x + pb0.y) + (pb1.x + pb1.y);                          \
        float kx = lo ? x4 : x5;                                               \
        float sx = lo ? x5 : x4;                                               \
        kx += __shfl_xor_sync(~0u, sx, 16);                                    \
        kx += __shfl_xor_sync(~0u, kx, 8);                                     \
        kx += __shfl_xor_sync(~0u, kx, 4);                                     \
        kx += __shfl_xor_sync(~0u, kx, 2);                                     \
        kx += __shfl_xor_sync(~0u, kx, 1);                                     \
        if (lane == 0)  sPart[(BUF) ^ 1][4][warp] = kx;                        \
        if (lane == 16) sPart[(BUF) ^ 1][5][warp] = kx;                        \
        /* state update */                                                     \
        _Pragma("unroll")                                                      \
        for (int j = 0; j < 3; j++) {                                          \
            h[j].x = tanha(fmaf(ghb, h[j].x, gha));                            \
            h[j].y = tanha(fmaf(ghb, h[j].y, gha));                            \
            h[j].z = tanha(fmaf(ghb, h[j].z, gha));                            \
            h[j].w = tanha(fmaf(ghb, h[j].w, gha));                            \
            c[j].x = tanha(fmaf(gcb, c[j].x, gca));                            \
            c[j].y = tanha(fmaf(gcb, c[j].y, gca));                            \
            c[j].z = tanha(fmaf(gcb, c[j].z, gca));                            \
            c[j].w = tanha(fmaf(gcb, c[j].w, gca));                            \
        }                                                                      \
        outp[0]   = h[0];                                                      \
        outp[128] = h[1];                                                      \
        outp[256] = h[2];                                                      \
        outp += BATCH * F4;                                                    \
    }

    // main loop: 248 steps, unrolled by 4 (static stage / parity)
    for (int tb = 0; tb < 248; tb += 4) {
        DO_STEP(2, 0, srcp); srcp += BATCH * F4;
        DO_STEP(3, 1, srcp); srcp += BATCH * F4;
        DO_STEP(0, 0, srcp); srcp += BATCH * F4;
        DO_STEP(1, 1, srcp); srcp += BATCH * F4;
    }
    // tail: steps 248..255 (x_254, x_255 real; later refills clamped to x_255)
    {
        const float4* srcL = in4 + (long)(T_STEPS - 1) * BATCH * F4
                           + (long)b * F4 + tid;
        DO_STEP(2, 0, srcp); srcp += BATCH * F4;   // t=248: loads x_254
        DO_STEP(3, 1, srcp);                        // t=249: loads x_255
        DO_STEP(0, 0, srcL);                        // t=250..255: clamped
        DO_STEP(1, 1, srcL);
        DO_STEP(2, 0, srcL);
        DO_STEP(3, 1, srcL);
        DO_STEP(0, 0, srcL);
        DO_STEP(1, 1, srcL);
    }
#undef DO_STEP

    // final hT, cT
    const long offH = (long)T_STEPS * BATCH * F4;
    const long offC = offH + (long)BATCH * F4;
    #pragma unroll
    for (int j = 0; j < 3; j++) {
        out4[offH + (long)b * F4 + tid + 128 * j] = h[j];
        out4[offC + (long)b * F4 + tid + 128 * j] = c[j];
    }
}

extern "C" void kernel_launch(void* const* d_in, const int* in_sizes, int n_in,
                              void* d_out, int out_size)
{
    const float* inputs = (const float*)d_in[0];
    const float* h0     = (const float*)d_in[1];
    const float* c0     = (const float*)d_in[2];
    const float* Wr     = (const float*)d_in[3];
    const float* br     = (const float*)d_in[4];
    const float* Wc     = (const float*)d_in[5];
    const float* bc     = (const float*)d_in[6];
    const float* Wi     = (const float*)d_in[7];
    const float* bi     = (const float*)d_in[8];
    float* out = (float*)d_out;

    fused_kernel<<<BATCH, NTHR>>>(inputs, h0, c0, Wr, br, Wc, bc, Wi, bi, out);
}

// round 15
// speedup vs baseline: 1.4439x; 1.4439x over previous
#include <cuda_runtime.h>
#include <cstdint>

#define T_STEPS 256
#define BATCH   128
#define KDIM    1536
#define F4      384     // KDIM/4 (float4 units)
#define NTHR    128
#define STAGES  4
#define STAGE_B 6144u   // F4 * 16 bytes

// HW tanh: single MUFU op, max rel err ~2^-11.
__device__ __forceinline__ float tanha(float x) {
    float y;
    asm("tanh.approx.f32 %0, %1;" : "=f"(y) : "f"(x));
    return y;
}

__device__ __forceinline__ void cp_async16(uint32_t dst, const void* src) {
    asm volatile("cp.async.cg.shared.global [%0], [%1], 16;" :: "r"(dst), "l"(src));
}
#define CP_COMMIT() asm volatile("cp.async.commit_group;" ::: "memory")
#define CP_WAIT2()  asm volatile("cp.async.wait_group 2;" ::: "memory")

// packed f32x2 fma
__device__ __forceinline__ void ffma2(unsigned long long& acc,
                                      unsigned long long a,
                                      unsigned long long b) {
    asm("fma.rn.f32x2 %0, %1, %2, %0;" : "+l"(acc) : "l"(a), "l"(b));
}
__device__ __forceinline__ float2 unpack2(unsigned long long v) {
    float2 f;
    asm("mov.b64 {%0, %1}, %2;" : "=f"(f.x), "=f"(f.y) : "l"(v));
    return f;
}

// 12-term dot product (3 float4 each side), 2 accumulator chains.
__device__ __forceinline__ float dot12(const float4* v, const float4* w) {
    float a0 = 0.0f, a1 = 0.0f;
    #pragma unroll
    for (int j = 0; j < 3; j++) {
        a0 = fmaf(v[j].x, w[j].x, fmaf(v[j].y, w[j].y, a0));
        a1 = fmaf(v[j].z, w[j].z, fmaf(v[j].w, w[j].w, a1));
    }
    return a0 + a1;
}

// ---------------------------------------------------------------------------
// One CTA per batch element, 128 threads (4 warps). Strided float4 ownership
// (tid + 128*j): fully coalesced. 4-stage cp.async input ring, unrolled by 4
// (static stages / parity / SMEM addresses), strength-reduced gmem pointers.
// Per step: 6-sum butterfly (9 SHFL, 5 levels), one STS per warp of its
// 6-sum chunk, one barrier, then EVERY lane computes all six finals itself
// from 8 broadcast LDS.128 (no lane roles, no broadcast SHFLs), 4 parallel
// tanh.approx for the gates, then the tanh.approx state update.
// ---------------------------------------------------------------------------
__global__ void __launch_bounds__(NTHR) fused_kernel(
    const float* __restrict__ inputs,
    const float* __restrict__ h0,
    const float* __restrict__ c0,
    const float* __restrict__ Wr,
    const float* __restrict__ br,
    const float* __restrict__ Wc,
    const float* __restrict__ bc,
    const float* __restrict__ Wi,
    const float* __restrict__ bi,
    float* __restrict__ out)
{
    __shared__ float      sPartW[2][4][8];    // [buf][warp][sum 0-5 + pad]
    __shared__ ulonglong2 sX[STAGES * F4];    // 4 x 6KB input stages (packed)

    const int tid  = threadIdx.x;
    const int b    = blockIdx.x;
    const int warp = tid >> 5;
    const int lane = tid & 31;

    const float4*     in4  = (const float4*)inputs;
    const float4*     Wr4  = (const float4*)Wr;
    const float4*     Wc4  = (const float4*)Wc;
    const ulonglong2* Wi2  = (const ulonglong2*)Wi;
    float4* out4 = (float4*)out;

    float4 h[3], c[3], wr0[3], wr1[3], wc0[3], wc1[3];
    ulonglong2 wi0p[3], wi1p[3];
    #pragma unroll
    for (int j = 0; j < 3; j++) {
        const int p = tid + 128 * j;           // strided ownership: coalesced
        h[j]    = ((const float4*)h0)[b * F4 + p];
        c[j]    = ((const float4*)c0)[b * F4 + p];
        wr0[j]  = Wr4[p];        wr1[j]  = Wr4[F4 + p];
        wc0[j]  = Wc4[p];        wc1[j]  = Wc4[F4 + p];
        wi0p[j] = Wi2[p];        wi1p[j] = Wi2[F4 + p];
    }
    // half-biases for the fused 0.5*(S+b) form
    const float hbr0 = 0.5f * br[0], hbr1 = 0.5f * br[1];
    const float hbc0 = 0.5f * bc[0], hbc1 = 0.5f * bc[1];
    const float bi0 = bi[0], bi1 = bi[1];

    // butterfly lane roles
    const bool lo  = lane < 16;
    const bool b3  = (lane & 8) != 0;
    const bool b2  = (lane & 4) != 0;
    const bool writer = lo ? ((lane & 3) == 0) : ((lane & 7) == 0);
    const int  widx   = lo ? (lane >> 2) : (4 + ((lane >> 3) & 1));

    const uint32_t sx_tid =
        (uint32_t)__cvta_generic_to_shared(&sX[0]) + (uint32_t)tid * 16u;
    const ulonglong2* sXu = &sX[0];

    // ---- prologue: X0 projection; fill stages 1..3 with x_1..x_3 ----
    {
        float4 x0[3];
        #pragma unroll
        for (int j = 0; j < 3; j++)
            x0[j] = in4[(long)b * F4 + tid + 128 * j];
        float4 wi0f[3], wi1f[3];
        #pragma unroll
        for (int j = 0; j < 3; j++) {
            wi0f[j] = *(const float4*)&wi0p[j];
            wi1f[j] = *(const float4*)&wi1p[j];
        }
        float v4 = dot12(x0, wi0f);
        float v5 = dot12(x0, wi1f);

        #pragma unroll
        for (int s = 1; s <= 3; s++) {
            const float4* src = in4 + (long)s * BATCH * F4 + (long)b * F4 + tid;
            const uint32_t dst = sx_tid + (uint32_t)s * STAGE_B;
            cp_async16(dst,         src);
            cp_async16(dst + 2048u, src + 128);
            cp_async16(dst + 4096u, src + 256);
            CP_COMMIT();
        }

        // full 5-level reduce for prologue (one-time)
        float k  = lo ? v4 : v5;
        float s_ = lo ? v5 : v4;
        k += __shfl_xor_sync(~0u, s_, 16);
        k += __shfl_xor_sync(~0u, k, 8);
        k += __shfl_xor_sync(~0u, k, 4);
        k += __shfl_xor_sync(~0u, k, 2);
        k += __shfl_xor_sync(~0u, k, 1);
        if (lane == 0)  sPartW[1][warp][4] = k;
        if (lane == 16) sPartW[1][warp][5] = k;
    }
    __syncthreads();
    float Xc, Xh;
    {
        Xc = (sPartW[1][0][4] + sPartW[1][1][4])
           + (sPartW[1][2][4] + sPartW[1][3][4]) + bi0;
        Xh = (sPartW[1][0][5] + sPartW[1][1][5])
           + (sPartW[1][2][5] + sPartW[1][3][5]) + bi1;
    }

    // strength-reduced pointers
    const float4* srcp = in4 + (long)4 * BATCH * F4 + (long)b * F4 + tid; // x_{t+4}
    float4*       outp = out4 + (long)b * F4 + tid;

#define DO_STEP(SC, SW, BUF, SRC)                                              \
    {                                                                          \
        CP_WAIT2();                                                            \
        const ulonglong2* xs = sXu + (SC) * F4 + tid;                          \
        ulonglong2 x0 = xs[0], x1 = xs[128], x2 = xs[256];                     \
        {   /* refill stage SW with x from SRC */                              \
            const uint32_t dst = sx_tid + (uint32_t)(SW) * STAGE_B;            \
            cp_async16(dst,         (SRC));                                    \
            cp_async16(dst + 2048u, (SRC) + 128);                              \
            cp_async16(dst + 4096u, (SRC) + 256);                              \
            CP_COMMIT();                                                       \
        }                                                                      \
        /* x-projection dots for t+1: packed FFMA2 */                          \
        unsigned long long a0 = 0ull, a1 = 0ull, q0_ = 0ull, q1_ = 0ull;       \
        ffma2(a0, x0.x, wi0p[0].x); ffma2(a1, x0.y, wi0p[0].y);                \
        ffma2(q0_, x0.x, wi1p[0].x); ffma2(q1_, x0.y, wi1p[0].y);              \
        ffma2(a0, x1.x, wi0p[1].x); ffma2(a1, x1.y, wi0p[1].y);                \
        ffma2(q0_, x1.x, wi1p[1].x); ffma2(q1_, x1.y, wi1p[1].y);              \
        ffma2(a0, x2.x, wi0p[2].x); ffma2(a1, x2.y, wi0p[2].y);                \
        ffma2(q0_, x2.x, wi1p[2].x); ffma2(q1_, x2.y, wi1p[2].y);              \
        float2 pa0 = unpack2(a0), pa1 = unpack2(a1);                           \
        float2 pb0 = unpack2(q0_), pb1 = unpack2(q1_);                         \
        float x4 = (pa0.x + pa0.y) + (pa1.x + pa1.y);                          \
        float x5 = (pb0.x + pb0.y) + (pb1.x + pb1.y);                          \
        /* gate dots */                                                        \
        float g0 = dot12(h, wr0), g1 = dot12(h, wr1);                          \
        float g2 = dot12(c, wc0), g3 = dot12(c, wc1);                          \
        /* 6-sum butterfly: 9 SHFL, 5 levels */                                \
        float rA = __shfl_xor_sync(~0u, lo ? x4 : g0, 16);                     \
        float rB = __shfl_xor_sync(~0u, lo ? x5 : g1, 16);                     \
        float rC = __shfl_xor_sync(~0u, g2, 16);                               \
        float rD = __shfl_xor_sync(~0u, g3, 16);                               \
        if (lo) { g0 += rA; g1 += rB; g2 += rC; g3 += rD; }                    \
        else    { x4 += rA; x5 += rB; }                                        \
        float P  = lo ? (b3 ? g2 : g0) : (b3 ? x5 : x4);                       \
        float sP = lo ? (b3 ? g0 : g2) : (b3 ? x4 : x5);                       \
        P += __shfl_xor_sync(~0u, sP, 8);                                      \
        float Q  = b3 ? g3 : g1;                                               \
        float sQ = b3 ? g1 : g3;                                               \
        Q += __shfl_xor_sync(~0u, sQ, 8);                                      \
        float R  = lo ? (b2 ? Q : P) : P;                                      \
        float sR = lo ? (b2 ? P : Q) : P;                                      \
        R += __shfl_xor_sync(~0u, sR, 4);                                      \
        R += __shfl_xor_sync(~0u, R, 2);                                       \
        R += __shfl_xor_sync(~0u, R, 1);                                       \
        if (writer) sPartW[BUF][warp][widx] = R;                               \
        __syncthreads();                                                       \
        /* tail: every lane loads all 4 warp-chunks (broadcast LDS.128) */     \
        const float4* cw = (const float4*)sPartW[BUF];                         \
        float4 A0 = cw[0], B0 = cw[1], A1 = cw[2], B1 = cw[3];                 \
        float4 A2 = cw[4], B2 = cw[5], A3 = cw[6], B3 = cw[7];                 \
        float4 fa;                                                             \
        fa.x = (A0.x + A1.x) + (A2.x + A3.x);                                  \
        fa.y = (A0.y + A1.y) + (A2.y + A3.y);                                  \
        fa.z = (A0.z + A1.z) + (A2.z + A3.z);                                  \
        fa.w = (A0.w + A1.w) + (A2.w + A3.w);                                  \
        float S4 = (B0.x + B1.x) + (B2.x + B3.x);                              \
        float S5 = (B0.y + B1.y) + (B2.y + B3.y);                              \
        /* 1 - sigmoid(S+b) = 0.5 - 0.5*tanh(0.5*S + 0.5*b) */                 \
        float sg0 = fmaf(-0.5f, tanha(fmaf(0.5f, fa.x, hbr0)), 0.5f);          \
        float sg1 = fmaf(-0.5f, tanha(fmaf(0.5f, fa.y, hbr1)), 0.5f);          \
        float sg2 = fmaf(-0.5f, tanha(fmaf(0.5f, fa.z, hbc0)), 0.5f);          \
        float sg3 = fmaf(-0.5f, tanha(fmaf(0.5f, fa.w, hbc1)), 0.5f);          \
        const float gca = sg0 * Xc;   /* (1-sig(Hc))*Xc */                     \
        const float ghb = sg1;        /* (1-sig(Hh))    */                     \
        const float gcb = sg2;        /* (1-sig(Cc))    */                     \
        const float gha = sg3 * Xh;   /* (1-sig(Ch))*Xh */                     \
        Xc = S4 + bi0;                                                         \
        Xh = S5 + bi1;                                                         \
        _Pragma("unroll")                                                      \
        for (int j = 0; j < 3; j++) {                                          \
            h[j].x = tanha(fmaf(ghb, h[j].x, gha));                            \
            h[j].y = tanha(fmaf(ghb, h[j].y, gha));                            \
            h[j].z = tanha(fmaf(ghb, h[j].z, gha));                            \
            h[j].w = tanha(fmaf(ghb, h[j].w, gha));                            \
            c[j].x = tanha(fmaf(gcb, c[j].x, gca));                            \
            c[j].y = tanha(fmaf(gcb, c[j].y, gca));                            \
            c[j].z = tanha(fmaf(gcb, c[j].z, gca));                            \
            c[j].w = tanha(fmaf(gcb, c[j].w, gca));                            \
            outp[128 * j] = h[j];                                              \
        }                                                                      \
        outp += BATCH * F4;                                                    \
    }

    // main loop: 252 steps, unrolled by 4 (static stages / buffer parity)
    for (int tb = 0; tb < 252; tb += 4) {
        DO_STEP(1, 0, 0, srcp); srcp += BATCH * F4;
        DO_STEP(2, 1, 1, srcp); srcp += BATCH * F4;
        DO_STEP(3, 2, 0, srcp); srcp += BATCH * F4;
        DO_STEP(0, 3, 1, srcp); srcp += BATCH * F4;
    }
    // tail: steps 252..255, refill source clamped to x_255
    {
        const float4* srcL = in4 + (long)(T_STEPS - 1) * BATCH * F4
                           + (long)b * F4 + tid;
        DO_STEP(1, 0, 0, srcL);
        DO_STEP(2, 1, 1, srcL);
        DO_STEP(3, 2, 0, srcL);
        DO_STEP(0, 3, 1, srcL);
    }
#undef DO_STEP

    // final hT, cT
    const long offH = (long)T_STEPS * BATCH * F4;
    const long offC = offH + (long)BATCH * F4;
    #pragma unroll
    for (int j = 0; j < 3; j++) {
        out4[offH + (long)b * F4 + tid + 128 * j] = h[j];
        out4[offC + (long)b * F4 + tid + 128 * j] = c[j];
    }
}

extern "C" void kernel_launch(void* const* d_in, const int* in_sizes, int n_in,
                              void* d_out, int out_size)
{
    const float* inputs = (const float*)d_in[0];
    const float* h0     = (const float*)d_in[1];
    const float* c0     = (const float*)d_in[2];
    const float* Wr     = (const float*)d_in[3];
    const float* br     = (const float*)d_in[4];
    const float* Wc     = (const float*)d_in[5];
    const float* bc     = (const float*)d_in[6];
    const float* Wi     = (const float*)d_in[7];
    const float* bi     = (const float*)d_in[8];
    float* out = (float*)d_out;

    fused_kernel<<<BATCH, NTHR>>>(inputs, h0, c0, Wr, br, Wc, bc, Wi, bi, out);
}

// round 16
// speedup vs baseline: 1.4477x; 1.0026x over previous
#include <cuda_runtime.h>
#include <cstdint>

#define T_STEPS 256
#define BATCH   128
#define KDIM    1536
#define F4      384     // KDIM/4 (float4 units)
#define NTHR    256     // warps 0-3 compute, warps 4-7 x-helpers
#define STAGE_B 6144u   // F4 * 16 bytes

// HW tanh: single MUFU op, max rel err ~2^-11.
__device__ __forceinline__ float tanha(float x) {
    float y;
    asm("tanh.approx.f32 %0, %1;" : "=f"(y) : "f"(x));
    return y;
}

__device__ __forceinline__ void cp_async16(uint32_t dst, const void* src) {
    asm volatile("cp.async.cg.shared.global [%0], [%1], 16;" :: "r"(dst), "l"(src));
}
#define CP_COMMIT() asm volatile("cp.async.commit_group;" ::: "memory")
#define CP_WAIT2()  asm volatile("cp.async.wait_group 2;" ::: "memory")

// packed f32x2 fma
__device__ __forceinline__ void ffma2(unsigned long long& acc,
                                      unsigned long long a,
                                      unsigned long long b) {
    asm("fma.rn.f32x2 %0, %1, %2, %0;" : "+l"(acc) : "l"(a), "l"(b));
}
__device__ __forceinline__ float2 unpack2(unsigned long long v) {
    float2 f;
    asm("mov.b64 {%0, %1}, %2;" : "=f"(f.x), "=f"(f.y) : "l"(v));
    return f;
}

// 12-term dot product (3 float4 each side), 2 accumulator chains.
__device__ __forceinline__ float dot12(const float4* v, const float4* w) {
    float a0 = 0.0f, a1 = 0.0f;
    #pragma unroll
    for (int j = 0; j < 3; j++) {
        a0 = fmaf(v[j].x, w[j].x, fmaf(v[j].y, w[j].y, a0));
        a1 = fmaf(v[j].z, w[j].z, fmaf(v[j].w, w[j].w, a1));
    }
    return a0 + a1;
}

// ---------------------------------------------------------------------------
// One CTA per batch, 256 threads. Warp-specialized:
//   warps 0-3 (compute): own h,c,Wr,Wc. Per step: gate dots -> 4-sum
//     butterfly (6 SHFL) -> STS -> barrier -> all-lanes tail (4 LDS.128
//     gates + 2 LDS.128 X) -> 4 gate tanh -> tanh state update + STG.
//   warps 4-7 (helpers): own Wi + the 4-stage cp.async input ring. Per step:
//     LDS x_{t+1}, refill ring, FFMA2 proj dots, 2-sum butterfly (5 SHFL),
//     STS into sXrow[(t+1)&1] — consumed by compute's NEXT-step tail.
// Each SMSP carries 1 compute + 1 helper warp with independent chains, so
// the helper's ~200-cyc chain hides inside compute's post-barrier phase.
// ---------------------------------------------------------------------------
__global__ void __launch_bounds__(NTHR) fused_kernel(
    const float* __restrict__ inputs,
    const float* __restrict__ h0,
    const float* __restrict__ c0,
    const float* __restrict__ Wr,
    const float* __restrict__ br,
    const float* __restrict__ Wc,
    const float* __restrict__ bc,
    const float* __restrict__ Wi,
    const float* __restrict__ bi,
    float* __restrict__ out)
{
    __shared__ float      sPartW[2][4][8];   // [buf][cwarp][gate 0-3 + pad]
    __shared__ float      sXrow[2][2][4];    // [slot][c/h][helper warp]
    __shared__ ulonglong2 sX[4 * F4];        // 4 x 6KB input stages (packed)

    const int tid  = threadIdx.x;
    const int b    = blockIdx.x;
    const int warp = tid >> 5;
    const int lane = tid & 31;
    const int htid = tid & 127;              // dim index within role
    const bool isC = warp < 4;
    const int  hw  = warp & 3;               // warp index within role

    const float4*     in4 = (const float4*)inputs;
    float4* out4 = (float4*)out;

    // ---- role-specific persistent registers ----
    float4 h[3], c[3], wr0[3], wr1[3], wc0[3], wc1[3];   // compute
    ulonglong2 wi0p[3], wi1p[3];                          // helpers
    if (isC) {
        const float4* Wr4 = (const float4*)Wr;
        const float4* Wc4 = (const float4*)Wc;
        #pragma unroll
        for (int j = 0; j < 3; j++) {
            const int p = htid + 128 * j;
            h[j]   = ((const float4*)h0)[b * F4 + p];
            c[j]   = ((const float4*)c0)[b * F4 + p];
            wr0[j] = Wr4[p];        wr1[j] = Wr4[F4 + p];
            wc0[j] = Wc4[p];        wc1[j] = Wc4[F4 + p];
        }
    } else {
        const ulonglong2* Wi2 = (const ulonglong2*)Wi;
        #pragma unroll
        for (int j = 0; j < 3; j++) {
            const int p = htid + 128 * j;
            wi0p[j] = Wi2[p];
            wi1p[j] = Wi2[F4 + p];
        }
    }
    const float hbr0 = 0.5f * br[0], hbr1 = 0.5f * br[1];
    const float hbc0 = 0.5f * bc[0], hbc1 = 0.5f * bc[1];
    const float bi0 = bi[0], bi1 = bi[1];

    // butterfly lane roles
    const bool lo = lane < 16;
    const bool b3 = (lane & 8) != 0;

    const uint32_t sx_tid =
        (uint32_t)__cvta_generic_to_shared(&sX[0]) + (uint32_t)htid * 16u;
    const ulonglong2* sXu = &sX[0];

    // ---- prologue ----
    // helpers: proj(x_0) -> sXrow[0]; fill stages 1..3 with x_1..x_3.
    if (!isC) {
        float4 x0[3], wi0f[3], wi1f[3];
        #pragma unroll
        for (int j = 0; j < 3; j++) {
            x0[j]   = in4[(long)b * F4 + htid + 128 * j];
            wi0f[j] = *(const float4*)&wi0p[j];
            wi1f[j] = *(const float4*)&wi1p[j];
        }
        float v4 = dot12(x0, wi0f);
        float v5 = dot12(x0, wi1f);

        #pragma unroll
        for (int s = 1; s <= 3; s++) {
            const float4* src = in4 + (long)s * BATCH * F4 + (long)b * F4 + htid;
            const uint32_t dst = sx_tid + (uint32_t)s * STAGE_B;
            cp_async16(dst,         src);
            cp_async16(dst + 2048u, src + 128);
            cp_async16(dst + 4096u, src + 256);
            CP_COMMIT();
        }

        float k  = lo ? v4 : v5;
        float s_ = lo ? v5 : v4;
        k += __shfl_xor_sync(~0u, s_, 16);
        k += __shfl_xor_sync(~0u, k, 8);
        k += __shfl_xor_sync(~0u, k, 4);
        k += __shfl_xor_sync(~0u, k, 2);
        k += __shfl_xor_sync(~0u, k, 1);
        if (lane == 0)  sXrow[0][0][hw] = k;
        if (lane == 16) sXrow[0][1][hw] = k;
    }
    __syncthreads();
    float Xc = 0.0f, Xh = 0.0f;
    if (isC) {
        float4 xc4 = *(const float4*)sXrow[0][0];
        float4 xh4 = *(const float4*)sXrow[0][1];
        Xc = (xc4.x + xc4.y) + (xc4.z + xc4.w) + bi0;
        Xh = (xh4.x + xh4.y) + (xh4.z + xh4.w) + bi1;
    }

    // strength-reduced pointers
    const float4* srcp = in4 + (long)4 * BATCH * F4 + (long)b * F4 + htid; // x_{t+4}
    float4*       outp = out4 + (long)b * F4 + htid;

#define DO_STEP(SC, SW, BUF, SLOT, SRC)                                        \
    {                                                                          \
        if (isC) {                                                             \
            /* gate dots + 4-sum butterfly (6 SHFL, 5 levels) */               \
            float g0 = dot12(h, wr0), g1 = dot12(h, wr1);                      \
            float g2 = dot12(c, wc0), g3 = dot12(c, wc1);                      \
            float rA = __shfl_xor_sync(~0u, lo ? g2 : g0, 16);                 \
            float rB = __shfl_xor_sync(~0u, lo ? g3 : g1, 16);                 \
            float u0 = (lo ? g0 : g2) + rA;                                    \
            float u1 = (lo ? g1 : g3) + rB;                                    \
            float keep = b3 ? u1 : u0;                                         \
            float send = b3 ? u0 : u1;                                         \
            float R = keep + __shfl_xor_sync(~0u, send, 8);                    \
            R += __shfl_xor_sync(~0u, R, 4);                                   \
            R += __shfl_xor_sync(~0u, R, 2);                                   \
            R += __shfl_xor_sync(~0u, R, 1);                                   \
            /* group [8k..8k+7] holds gate k: writers lanes 0,8,16,24 */       \
            if ((lane & 7) == 0) sPartW[BUF][hw][lane >> 3] = R;               \
        } else {                                                               \
            /* helpers: x-projection for step t+1 */                           \
            CP_WAIT2();                                                        \
            const ulonglong2* xs = sXu + (SC) * F4 + htid;                     \
            ulonglong2 x0 = xs[0], x1 = xs[128], x2 = xs[256];                 \
            {   /* refill stage SW with x from SRC */                          \
                const uint32_t dst = sx_tid + (uint32_t)(SW) * STAGE_B;        \
                cp_async16(dst,         (SRC));                                \
                cp_async16(dst + 2048u, (SRC) + 128);                          \
                cp_async16(dst + 4096u, (SRC) + 256);                          \
                CP_COMMIT();                                                   \
            }                                                                  \
            unsigned long long a0 = 0ull, a1 = 0ull, q0 = 0ull, q1 = 0ull;     \
            ffma2(a0, x0.x, wi0p[0].x); ffma2(a1, x0.y, wi0p[0].y);            \
            ffma2(q0, x0.x, wi1p[0].x); ffma2(q1, x0.y, wi1p[0].y);            \
            ffma2(a0, x1.x, wi0p[1].x); ffma2(a1, x1.y, wi0p[1].y);            \
            ffma2(q0, x1.x, wi1p[1].x); ffma2(q1, x1.y, wi1p[1].y);            \
            ffma2(a0, x2.x, wi0p[2].x); ffma2(a1, x2.y, wi0p[2].y);            \
            ffma2(q0, x2.x, wi1p[2].x); ffma2(q1, x2.y, wi1p[2].y);            \
            float2 pa0 = unpack2(a0), pa1 = unpack2(a1);                       \
            float2 pb0 = unpack2(q0), pb1 = unpack2(q1);                       \
            float x4 = (pa0.x + pa0.y) + (pa1.x + pa1.y);                      \
            float x5 = (pb0.x + pb0.y) + (pb1.x + pb1.y);                      \
            float k  = lo ? x4 : x5;                                           \
            float s_ = lo ? x5 : x4;                                           \
            k += __shfl_xor_sync(~0u, s_, 16);                                 \
            k += __shfl_xor_sync(~0u, k, 8);                                   \
            k += __shfl_xor_sync(~0u, k, 4);                                   \
            k += __shfl_xor_sync(~0u, k, 2);                                   \
            k += __shfl_xor_sync(~0u, k, 1);                                   \
            if (lane == 0)  sXrow[SLOT][0][hw] = k;                            \
            if (lane == 16) sXrow[SLOT][1][hw] = k;                            \
        }                                                                      \
        __syncthreads();                                                       \
        if (isC) {                                                             \
            /* tail: 4 warp-chunks of gates + next-step X (broadcast LDS) */   \
            const float4* cw = (const float4*)sPartW[BUF];                     \
            float4 A0 = cw[0], A1 = cw[2], A2 = cw[4], A3 = cw[6];             \
            float4 fa;                                                         \
            fa.x = (A0.x + A1.x) + (A2.x + A3.x);                              \
            fa.y = (A0.y + A1.y) + (A2.y + A3.y);                              \
            fa.z = (A0.z + A1.z) + (A2.z + A3.z);                              \
            fa.w = (A0.w + A1.w) + (A2.w + A3.w);                              \
            float4 xc4 = *(const float4*)sXrow[SLOT][0];                       \
            float4 xh4 = *(const float4*)sXrow[SLOT][1];                       \
            /* 1 - sigmoid(S+b) = 0.5 - 0.5*tanh(0.5*S + 0.5*b) */             \
            float sg0 = fmaf(-0.5f, tanha(fmaf(0.5f, fa.x, hbr0)), 0.5f);      \
            float sg1 = fmaf(-0.5f, tanha(fmaf(0.5f, fa.y, hbr1)), 0.5f);      \
            float sg2 = fmaf(-0.5f, tanha(fmaf(0.5f, fa.z, hbc0)), 0.5f);      \
            float sg3 = fmaf(-0.5f, tanha(fmaf(0.5f, fa.w, hbc1)), 0.5f);      \
            const float gca = sg0 * Xc;   /* (1-sig(Hc))*Xc */                 \
            const float ghb = sg1;        /* (1-sig(Hh))    */                 \
            const float gcb = sg2;        /* (1-sig(Cc))    */                 \
            const float gha = sg3 * Xh;   /* (1-sig(Ch))*Xh */                 \
            Xc = (xc4.x + xc4.y) + (xc4.z + xc4.w) + bi0;                      \
            Xh = (xh4.x + xh4.y) + (xh4.z + xh4.w) + bi1;                      \
            _Pragma("unroll")                                                  \
            for (int j = 0; j < 3; j++) {                                      \
                h[j].x = tanha(fmaf(ghb, h[j].x, gha));                        \
                h[j].y = tanha(fmaf(ghb, h[j].y, gha));                        \
                h[j].z = tanha(fmaf(ghb, h[j].z, gha));                        \
                h[j].w = tanha(fmaf(ghb, h[j].w, gha));                        \
                c[j].x = tanha(fmaf(gcb, c[j].x, gca));                        \
                c[j].y = tanha(fmaf(gcb, c[j].y, gca));                        \
                c[j].z = tanha(fmaf(gcb, c[j].z, gca));                        \
                c[j].w = tanha(fmaf(gcb, c[j].w, gca));                        \
                outp[128 * j] = h[j];                                          \
            }                                                                  \
        }                                                                      \
        outp += BATCH * F4;                                                    \
    }

    // main loop: 252 steps, unrolled by 4 (static stage / parity / slot)
    for (int tb = 0; tb < 252; tb += 4) {
        DO_STEP(1, 0, 0, 1, srcp); srcp += BATCH * F4;
        DO_STEP(2, 1, 1, 0, srcp); srcp += BATCH * F4;
        DO_STEP(3, 2, 0, 1, srcp); srcp += BATCH * F4;
        DO_STEP(0, 3, 1, 0, srcp); srcp += BATCH * F4;
    }
    // tail: steps 252..255, refill source clamped to x_255
    {
        const float4* srcL = in4 + (long)(T_STEPS - 1) * BATCH * F4
                           + (long)b * F4 + htid;
        DO_STEP(1, 0, 0, 1, srcL);
        DO_STEP(2, 1, 1, 0, srcL);
        DO_STEP(3, 2, 0, 1, srcL);
        DO_STEP(0, 3, 1, 0, srcL);
    }
#undef DO_STEP

    // final hT, cT (compute warps hold the state)
    if (isC) {
        const long offH = (long)T_STEPS * BATCH * F4;
        const long offC = offH + (long)BATCH * F4;
        #pragma unroll
        for (int j = 0; j < 3; j++) {
            out4[offH + (long)b * F4 + htid + 128 * j] = h[j];
            out4[offC + (long)b * F4 + htid + 128 * j] = c[j];
        }
    }
}

extern "C" void kernel_launch(void* const* d_in, const int* in_sizes, int n_in,
                              void* d_out, int out_size)
{
    const float* inputs = (const float*)d_in[0];
    const float* h0     = (const float*)d_in[1];
    const float* c0     = (const float*)d_in[2];
    const float* Wr     = (const float*)d_in[3];
    const float* br     = (const float*)d_in[4];
    const float* Wc     = (const float*)d_in[5];
    const float* bc     = (const float*)d_in[6];
    const float* Wi     = (const float*)d_in[7];
    const float* bi     = (const float*)d_in[8];
    float* out = (float*)d_out;

    fused_kernel<<<BATCH, NTHR>>>(inputs, h0, c0, Wr, br, Wc, bc, Wi, bi, out);
}